// round 14
// baseline (speedup 1.0000x reference)
#include <cuda_runtime.h>
#include <cuda_fp16.h>
#include <cstdint>
#include <cstddef>

#define NN   50000
#define EE   800000
#define RR   4
#define NB   (NN * RR)
#define DIN  128
#define DH   256
#define EPSF 1e-10f

// ---------------- scratch (static device globals) ------------------------------
__device__ int   g_deg[NB];
__device__ int   g_off[NB];
__device__ int   g_pos[NB];
__device__ int   g_bsum[256];
__device__ int   g_eidx[EE];

// single-plane fp16 operands
__device__ uint16_t g_xf[(size_t)NN * DIN];
__device__ uint16_t g_aggf[(size_t)NN * RR * DH];
__device__ uint16_t g_tf[(size_t)NN * DH];
__device__ uint16_t g_hf16[(size_t)NN * DH];

#define OW_REL1  0
#define OW_LOOP1 131072
#define OW_HP1   163840
#define OW_HT1   229376
#define OW_REL2  294912
#define OW_LOOP2 557056
#define OW_HP2   622592
#define OW_HT2   688128
#define WTOT     753664
__device__ uint16_t g_wf[WTOT];      // fp16 weights

// ---------------- CSR build ------------------------------------------------------
__global__ void zero_deg_pos() {
    int i = blockIdx.x * blockDim.x + threadIdx.x;
    if (i < NB) { g_deg[i] = 0; g_pos[i] = 0; }
}

__global__ void count_kernel(const int* __restrict__ dst, const int* __restrict__ rel, int E) {
    int e = blockIdx.x * blockDim.x + threadIdx.x;
    if (e < E) atomicAdd(&g_deg[dst[e] * RR + rel[e]], 1);
}

__global__ void scan_block(const int* __restrict__ in, int* __restrict__ out,
                           int* __restrict__ bsum, int n) {
    __shared__ int wsum[8];
    int base = blockIdx.x * 1024;
    int t = threadIdx.x;
    int lane = t & 31, w = t >> 5;
    int v[4], s = 0;
#pragma unroll
    for (int j = 0; j < 4; j++) {
        int i = base + t * 4 + j;
        v[j] = (i < n) ? in[i] : 0;
        s += v[j];
    }
    int ps = s;
#pragma unroll
    for (int d = 1; d < 32; d <<= 1) {
        int y = __shfl_up_sync(~0u, ps, d);
        if (lane >= d) ps += y;
    }
    if (lane == 31) wsum[w] = ps;
    __syncthreads();
    if (w == 0) {
        int x = (lane < 8) ? wsum[lane] : 0;
#pragma unroll
        for (int d = 1; d < 8; d <<= 1) {
            int y = __shfl_up_sync(~0u, x, d);
            if (lane >= d) x += y;
        }
        if (lane < 8) wsum[lane] = x;
    }
    __syncthreads();
    int excl = ps - s + (w > 0 ? wsum[w - 1] : 0);
#pragma unroll
    for (int j = 0; j < 4; j++) {
        int i = base + t * 4 + j;
        if (i < n) out[i] = excl;
        excl += v[j];
    }
    if (t == 255 && bsum) bsum[blockIdx.x] = (w > 0 ? wsum[w - 1] : 0) + ps;
}

__global__ void scan_add(int* __restrict__ off, const int* __restrict__ bsum, int n) {
    int i = blockIdx.x * 1024 + threadIdx.x * 4;
    int a = bsum[blockIdx.x];
#pragma unroll
    for (int j = 0; j < 4; j++)
        if (i + j < n) off[i + j] += a;
}

__global__ void place_kernel(const int* __restrict__ src, const int* __restrict__ dst,
                             const int* __restrict__ rel, int E) {
    int e = blockIdx.x * blockDim.x + threadIdx.x;
    if (e >= E) return;
    int b = dst[e] * RR + rel[e];
    int slot = g_off[b] + atomicAdd(&g_pos[b], 1);
    g_eidx[slot] = src[e];
}

// ---------------- conversions -------------------------------------------------------
__global__ void split_all_w(const float* w0, const float* w1, const float* w2,
                            const float* w3, const float* w4, const float* w5,
                            const float* w6, const float* w7) {
    const int offs[8]  = {OW_REL1, OW_LOOP1, OW_HP1, OW_HT1,
                          OW_REL2, OW_LOOP2, OW_HP2, OW_HT2};
    const int sizes[8] = {131072, 32768, 65536, 65536, 262144, 65536, 65536, 65536};
    int seg = blockIdx.y;
    const float* w;
    switch (seg) {
        case 0: w = w0; break; case 1: w = w1; break;
        case 2: w = w2; break; case 3: w = w3; break;
        case 4: w = w4; break; case 5: w = w5; break;
        case 6: w = w6; break; default: w = w7; break;
    }
    int n = sizes[seg];
    int o = offs[seg];
    for (int i = blockIdx.x * blockDim.x + threadIdx.x; i < n; i += gridDim.x * blockDim.x)
        g_wf[o + i] = __half_as_ushort(__float2half_rn(w[i]));
}

__global__ void convert_x(const float* __restrict__ w, int n) {
    int i = blockIdx.x * blockDim.x + threadIdx.x;
    if (i >= n) return;
    g_xf[i] = __half_as_ushort(__float2half_rn(w[i]));
}

// ---------------- gather aggregation (fp16 source, MLP=4 unrolled) -------------------
template <int D>
__global__ void agg_gather(const uint16_t* __restrict__ xf) {
    constexpr int W32 = D / 64;               // uint32 words per lane: 2 or 4
    int gw = (blockIdx.x * blockDim.x + threadIdx.x) >> 5;
    int lane = threadIdx.x & 31;
    if (gw >= NB) return;
    int start = g_off[gw];
    int n = g_deg[gw];
    float acc[2 * W32];
#pragma unroll
    for (int j = 0; j < 2 * W32; ++j) acc[j] = 0.f;

    auto accum_word = [&](uint32_t w, int j) {
        __half2 h2 = *(__half2*)&w;
        float2 f = __half22float2(h2);
        acc[2 * j + 0] += f.x;
        acc[2 * j + 1] += f.y;
    };

    int k = 0;
    for (; k + 4 <= n; k += 4) {
        int s0 = g_eidx[start + k + 0];
        int s1 = g_eidx[start + k + 1];
        int s2 = g_eidx[start + k + 2];
        int s3 = g_eidx[start + k + 3];
        if (D == 256) {
            uint4 v0 = ((const uint4*)(xf + (size_t)s0 * D))[lane];
            uint4 v1 = ((const uint4*)(xf + (size_t)s1 * D))[lane];
            uint4 v2 = ((const uint4*)(xf + (size_t)s2 * D))[lane];
            uint4 v3 = ((const uint4*)(xf + (size_t)s3 * D))[lane];
            accum_word(v0.x, 0); accum_word(v0.y, 1); accum_word(v0.z, 2); accum_word(v0.w, 3);
            accum_word(v1.x, 0); accum_word(v1.y, 1); accum_word(v1.z, 2); accum_word(v1.w, 3);
            accum_word(v2.x, 0); accum_word(v2.y, 1); accum_word(v2.z, 2); accum_word(v2.w, 3);
            accum_word(v3.x, 0); accum_word(v3.y, 1); accum_word(v3.z, 2); accum_word(v3.w, 3);
        } else {
            uint2 v0 = ((const uint2*)(xf + (size_t)s0 * D))[lane];
            uint2 v1 = ((const uint2*)(xf + (size_t)s1 * D))[lane];
            uint2 v2 = ((const uint2*)(xf + (size_t)s2 * D))[lane];
            uint2 v3 = ((const uint2*)(xf + (size_t)s3 * D))[lane];
            accum_word(v0.x, 0); accum_word(v0.y, 1);
            accum_word(v1.x, 0); accum_word(v1.y, 1);
            accum_word(v2.x, 0); accum_word(v2.y, 1);
            accum_word(v3.x, 0); accum_word(v3.y, 1);
        }
    }
    for (; k + 2 <= n; k += 2) {
        int s0 = g_eidx[start + k + 0];
        int s1 = g_eidx[start + k + 1];
        if (D == 256) {
            uint4 v0 = ((const uint4*)(xf + (size_t)s0 * D))[lane];
            uint4 v1 = ((const uint4*)(xf + (size_t)s1 * D))[lane];
            accum_word(v0.x, 0); accum_word(v0.y, 1); accum_word(v0.z, 2); accum_word(v0.w, 3);
            accum_word(v1.x, 0); accum_word(v1.y, 1); accum_word(v1.z, 2); accum_word(v1.w, 3);
        } else {
            uint2 v0 = ((const uint2*)(xf + (size_t)s0 * D))[lane];
            uint2 v1 = ((const uint2*)(xf + (size_t)s1 * D))[lane];
            accum_word(v0.x, 0); accum_word(v0.y, 1);
            accum_word(v1.x, 0); accum_word(v1.y, 1);
        }
    }
    if (k < n) {
        int s0 = g_eidx[start + k];
        if (D == 256) {
            uint4 v0 = ((const uint4*)(xf + (size_t)s0 * D))[lane];
            accum_word(v0.x, 0); accum_word(v0.y, 1); accum_word(v0.z, 2); accum_word(v0.w, 3);
        } else {
            uint2 v0 = ((const uint2*)(xf + (size_t)s0 * D))[lane];
            accum_word(v0.x, 0); accum_word(v0.y, 1);
        }
    }

    float inv = 1.0f / ((float)n + EPSF);
    uint32_t o[W32];
#pragma unroll
    for (int j = 0; j < W32; ++j) {
        __half2 h2 = __floats2half2_rn(acc[2 * j] * inv, acc[2 * j + 1] * inv);
        o[j] = *(uint32_t*)&h2;
    }
    if (D == 256) {
        uint4 v = make_uint4(o[0], o[1], o[2], o[3]);
        ((uint4*)(g_aggf + (size_t)gw * D))[lane] = v;
    } else {
        uint2 v = make_uint2(o[0], o[1]);
        ((uint2*)(g_aggf + (size_t)gw * D))[lane] = v;
    }
}

// ---------------- mma.sync / cp.async helpers ----------------------------------------
__device__ __forceinline__ uint32_t smem_u32(const void* p) {
    uint32_t a;
    asm("{ .reg .u64 t; cvta.to.shared.u64 t, %1; cvt.u32.u64 %0, t; }" : "=r"(a) : "l"(p));
    return a;
}
__device__ __forceinline__ void ldsm_x4(uint32_t* r, uint32_t addr) {
    asm volatile("ldmatrix.sync.aligned.m8n8.x4.shared.b16 {%0,%1,%2,%3}, [%4];"
                 : "=r"(r[0]), "=r"(r[1]), "=r"(r[2]), "=r"(r[3]) : "r"(addr));
}
__device__ __forceinline__ void ldsm_x4_t(uint32_t* r, uint32_t addr) {
    asm volatile("ldmatrix.sync.aligned.m8n8.x4.trans.shared.b16 {%0,%1,%2,%3}, [%4];"
                 : "=r"(r[0]), "=r"(r[1]), "=r"(r[2]), "=r"(r[3]) : "r"(addr));
}
__device__ __forceinline__ void mma_f16(float* d, const uint32_t* a, uint32_t b0, uint32_t b1) {
    asm volatile(
        "mma.sync.aligned.m16n8k16.row.col.f32.f16.f16.f32 "
        "{%0,%1,%2,%3}, {%4,%5,%6,%7}, {%8,%9}, {%0,%1,%2,%3};"
        : "+f"(d[0]), "+f"(d[1]), "+f"(d[2]), "+f"(d[3])
        : "r"(a[0]), "r"(a[1]), "r"(a[2]), "r"(a[3]), "r"(b0), "r"(b1));
}
__device__ __forceinline__ void cp16(uint32_t dst, const void* src, bool pred) {
    int sz = pred ? 16 : 0;
    asm volatile("cp.async.cg.shared.global [%0], [%1], 16, %2;"
                 :: "r"(dst), "l"(src), "r"(sz) : "memory");
}
#define CP_COMMIT() asm volatile("cp.async.commit_group;" ::: "memory")
#define CP_WAIT1()  asm volatile("cp.async.wait_group 1;" ::: "memory")

// ---------------- RGC dual-A GEMM (fp16 single-plane, 3 CTAs/SM) -----------------------
#define NSTG 3
#define A_STRIDE 48
#define A_BYTES  (128 * A_STRIDE)          // 6144
#define B_BYTES  4096
#define STAGE_BYTES (A_BYTES + B_BYTES)    // 10240
#define GEMM_SMEM (NSTG * STAGE_BYTES)     // 30720

__global__ void __launch_bounds__(256, 3)
gemm_mma(const uint16_t* __restrict__ A1f, int K1, const uint16_t* __restrict__ W1,
         const uint16_t* __restrict__ A2f, int K2, const uint16_t* __restrict__ W2,
         const float* __restrict__ b1, const float* __restrict__ b2,
         uint16_t* __restrict__ Cf16, int M, int ldc) {
    extern __shared__ char sm[];
    uint32_t smBase = smem_u32(sm);

    int tid  = threadIdx.x;
    int warp = tid >> 5;
    int lane = tid & 31;
    int warpM = warp >> 1;
    int warpN = warp & 1;
    int rowBase = blockIdx.x * 128;
    int colBase = blockIdx.y * 128;

    float acc[2][8][4];
#pragma unroll
    for (int i = 0; i < 2; i++)
#pragma unroll
        for (int j = 0; j < 8; j++)
#pragma unroll
            for (int q = 0; q < 4; q++) acc[i][j][q] = 0.f;

    int nt1 = K1 >> 4, nt2 = K2 >> 4;
    int nt = nt1 + nt2;

    int aRow  = tid >> 1, aHalf = tid & 1;
    int bR    = (tid >> 4) & 15;
    int bC16  = tid & 15;

    auto issue_stage = [&](int t) {
        uint32_t stg = smBase + (uint32_t)(t % NSTG) * STAGE_BYTES;
        const uint16_t *Af, *W;
        int K, k0;
        if (t < nt1) { Af = A1f; W = W1; K = K1; k0 = t * 16; }
        else { Af = A2f; W = W2; K = K2; k0 = (t - nt1) * 16; }
        {
            int gr = rowBase + aRow;
            bool ok = gr < M;
            int grc = ok ? gr : (M - 1);
            cp16(stg + aRow * A_STRIDE + aHalf * 16,
                 Af + (size_t)grc * K + k0 + aHalf * 8, ok);
        }
        {
            uint32_t dst = stg + A_BYTES + bR * 256
                         + ((uint32_t)(bC16 * 16) ^ ((bR & 7) << 4));
            cp16(dst, W + (size_t)(k0 + bR) * DH + colBase + bC16 * 8, true);
        }
    };

    issue_stage(0); CP_COMMIT();
    if (nt > 1) issue_stage(1);
    CP_COMMIT();

    for (int t = 0; t < nt; ++t) {
        CP_WAIT1();
        __syncthreads();

        if (t + 2 < nt) issue_stage(t + 2);
        CP_COMMIT();

        uint32_t stg = smBase + (uint32_t)(t % NSTG) * STAGE_BYTES;
        uint32_t aBase = stg;
        uint32_t bBase = stg + A_BYTES;

        uint32_t a[2][4];
#pragma unroll
        for (int mt = 0; mt < 2; ++mt) {
            int row = warpM * 32 + mt * 16 + (lane & 15);
            uint32_t ad = aBase + row * A_STRIDE + (lane >> 4) * 16;
            ldsm_x4(a[mt], ad);
        }
#pragma unroll
        for (int bt = 0; bt < 4; ++bt) {
            int k = lane & 15;
            uint32_t cb = (uint32_t)(warpN * 128 + bt * 32 + (lane >> 4) * 16);
            uint32_t bd = bBase + k * 256 + (cb ^ ((k & 7) << 4));
            uint32_t b[4];
            ldsm_x4_t(b, bd);
#pragma unroll
            for (int mt = 0; mt < 2; ++mt) {
                mma_f16(acc[mt][bt * 2 + 0], a[mt], b[0], b[1]);
                mma_f16(acc[mt][bt * 2 + 1], a[mt], b[2], b[3]);
            }
        }
        __syncthreads();
    }

    // epilogue: relu(acc + b1 + b2) -> fp16 plane
#pragma unroll
    for (int mt = 0; mt < 2; ++mt) {
        int r0 = rowBase + warpM * 32 + mt * 16 + (lane >> 2);
#pragma unroll
        for (int j = 0; j < 8; ++j) {
            int col = colBase + warpN * 64 + j * 8 + (lane & 3) * 2;
            float bias0 = b1[col] + b2[col];
            float bias1 = b1[col + 1] + b2[col + 1];
            float v0 = fmaxf(acc[mt][j][0] + bias0, 0.f);
            float v1 = fmaxf(acc[mt][j][1] + bias1, 0.f);
            float v2 = fmaxf(acc[mt][j][2] + bias0, 0.f);
            float v3 = fmaxf(acc[mt][j][3] + bias1, 0.f);
            if (r0 < M)
                *(uint32_t*)(Cf16 + (size_t)r0 * ldc + col) =
                    (uint32_t)__half_as_ushort(__float2half_rn(v0)) |
                    ((uint32_t)__half_as_ushort(__float2half_rn(v1)) << 16);
            if (r0 + 8 < M)
                *(uint32_t*)(Cf16 + (size_t)(r0 + 8) * ldc + col) =
                    (uint32_t)__half_as_ushort(__float2half_rn(v2)) |
                    ((uint32_t)__half_as_ushort(__float2half_rn(v3)) << 16);
        }
    }
}

// ---------------- fused highway GEMM (fp16 single-plane) -------------------------------
#define HW_NT 16
#define HWB_BYTES 8192
#define HW_STAGE (A_BYTES + HWB_BYTES)     // 14336
#define HW_SMEM (NSTG * HW_STAGE)          // 43008

__global__ void __launch_bounds__(512, 1)
hw_gemm(const uint16_t* __restrict__ Af,
        const uint16_t* __restrict__ Wp, const uint16_t* __restrict__ Wg,
        const float* __restrict__ bp, const float* __restrict__ bg,
        float* __restrict__ hf, uint16_t* __restrict__ hf16, int M) {
    extern __shared__ char sm[];
    uint32_t smBase = smem_u32(sm);

    int tid  = threadIdx.x;
    int warp = tid >> 5;
    int lane = tid & 31;
    int warpM = warp >> 2;
    int warpN = warp & 3;
    int rowBase = blockIdx.x * 128;
    int colBase = blockIdx.y * 128;

    float accp[2][4][4], accg[2][4][4];
#pragma unroll
    for (int i = 0; i < 2; i++)
#pragma unroll
        for (int j = 0; j < 4; j++)
#pragma unroll
            for (int q = 0; q < 4; q++) { accp[i][j][q] = 0.f; accg[i][j][q] = 0.f; }

    auto issue_stage = [&](int t) {
        uint32_t stg = smBase + (uint32_t)(t % NSTG) * HW_STAGE;
        int k0 = t * 16;
        if (tid < 256) {
            int aRow = tid >> 1, aHalf = tid & 1;
            int gr = rowBase + aRow;
            bool ok = gr < M;
            int grc = ok ? gr : (M - 1);
            cp16(stg + aRow * A_STRIDE + aHalf * 16,
                 Af + (size_t)grc * DH + k0 + aHalf * 8, ok);
        }
        {
            int set = tid >> 8;
            int r   = (tid >> 4) & 15;
            int c16 = tid & 15;
            const uint16_t* base = set ? Wg : Wp;
            uint32_t dst = stg + A_BYTES + set * 4096 + r * 256
                         + ((uint32_t)(c16 * 16) ^ ((r & 7) << 4));
            cp16(dst, base + (size_t)(k0 + r) * DH + colBase + c16 * 8, true);
        }
    };

    issue_stage(0); CP_COMMIT();
    issue_stage(1); CP_COMMIT();

    for (int t = 0; t < HW_NT; ++t) {
        CP_WAIT1();
        __syncthreads();

        if (t + 2 < HW_NT) issue_stage(t + 2);
        CP_COMMIT();

        uint32_t stg = smBase + (uint32_t)(t % NSTG) * HW_STAGE;
        uint32_t aBase = stg;
        uint32_t bBase = stg + A_BYTES;

        uint32_t a[2][4];
#pragma unroll
        for (int mt = 0; mt < 2; ++mt) {
            int row = warpM * 32 + mt * 16 + (lane & 15);
            uint32_t ad = aBase + row * A_STRIDE + (lane >> 4) * 16;
            ldsm_x4(a[mt], ad);
        }
        int k = lane & 15;
#pragma unroll
        for (int bt = 0; bt < 2; ++bt) {
            uint32_t cb = (uint32_t)(warpN * 64 + bt * 32 + (lane >> 4) * 16);
            uint32_t bd0 = bBase + k * 256 + (cb ^ ((k & 7) << 4));
            uint32_t b[4];
            ldsm_x4_t(b, bd0);                 // proj
#pragma unroll
            for (int mt = 0; mt < 2; ++mt) {
                mma_f16(accp[mt][bt * 2 + 0], a[mt], b[0], b[1]);
                mma_f16(accp[mt][bt * 2 + 1], a[mt], b[2], b[3]);
            }
            ldsm_x4_t(b, bd0 + 4096);          // gate
#pragma unroll
            for (int mt = 0; mt < 2; ++mt) {
                mma_f16(accg[mt][bt * 2 + 0], a[mt], b[0], b[1]);
                mma_f16(accg[mt][bt * 2 + 1], a[mt], b[2], b[3]);
            }
        }
        __syncthreads();
    }

    // fused highway epilogue (t residual re-read from fp16 plane)
#pragma unroll
    for (int mt = 0; mt < 2; ++mt) {
        int r0 = rowBase + warpM * 32 + mt * 16 + (lane >> 2);
#pragma unroll
        for (int j = 0; j < 4; ++j) {
            int col = colBase + warpN * 32 + j * 8 + (lane & 3) * 2;
            float bp0 = bp[col], bp1 = bp[col + 1];
            float bg0 = bg[col], bg1 = bg[col + 1];
#pragma unroll
            for (int half = 0; half < 2; ++half) {
                int r = r0 + half * 8;
                if (r >= M) continue;
                float p0 = fmaxf(accp[mt][j][half * 2 + 0] + bp0, 0.f);
                float p1 = fmaxf(accp[mt][j][half * 2 + 1] + bp1, 0.f);
                float q0 = accg[mt][j][half * 2 + 0] + bg0;
                float q1 = accg[mt][j][half * 2 + 1] + bg1;
                float s0 = 1.0f / (1.0f + expf(-q0));
                float s1 = 1.0f / (1.0f + expf(-q1));
                uint32_t tw = *(const uint32_t*)(Af + (size_t)r * DH + col);
                float t0 = __half2float(__ushort_as_half((uint16_t)(tw & 0xFFFF)));
                float t1 = __half2float(__ushort_as_half((uint16_t)(tw >> 16)));
                float v0 = s0 * p0 + (1.0f - s0) * t0;
                float v1 = s1 * p1 + (1.0f - s1) * t1;
                if (hf) *(float2*)(hf + (size_t)r * DH + col) = make_float2(v0, v1);
                if (hf16)
                    *(uint32_t*)(hf16 + (size_t)r * DH + col) =
                        (uint32_t)__half_as_ushort(__float2half_rn(v0)) |
                        ((uint32_t)__half_as_ushort(__float2half_rn(v1)) << 16);
            }
        }
    }
}

// ---------------- launcher ------------------------------------------------------------
extern "C" void kernel_launch(void* const* d_in, const int* in_sizes, int n_in,
                              void* d_out, int out_size) {
    const float* x       = (const float*)d_in[0];
    const int*   src     = (const int*)d_in[1];
    const int*   dst     = (const int*)d_in[2];
    const int*   rel     = (const int*)d_in[3];
    const float* rel_w1  = (const float*)d_in[4];
    const float* rel_b1  = (const float*)d_in[5];
    const float* loop_w1 = (const float*)d_in[6];
    const float* loop_b1 = (const float*)d_in[7];
    const float* hp_w1   = (const float*)d_in[8];
    const float* hp_b1   = (const float*)d_in[9];
    const float* ht_w1   = (const float*)d_in[10];
    const float* ht_b1   = (const float*)d_in[11];
    const float* rel_w2  = (const float*)d_in[12];
    const float* rel_b2  = (const float*)d_in[13];
    const float* loop_w2 = (const float*)d_in[14];
    const float* loop_b2 = (const float*)d_in[15];
    const float* hp_w2   = (const float*)d_in[16];
    const float* hp_b2   = (const float*)d_in[17];
    const float* ht_w2   = (const float*)d_in[18];
    const float* ht_b2   = (const float*)d_in[19];
    float* out = (float*)d_out;

    int *deg, *off, *pos, *bsum;
    uint16_t *wf, *xf, *aggf, *tf, *hf16;
    cudaGetSymbolAddress((void**)&deg,  g_deg);
    cudaGetSymbolAddress((void**)&off,  g_off);
    cudaGetSymbolAddress((void**)&pos,  g_pos);
    cudaGetSymbolAddress((void**)&bsum, g_bsum);
    cudaGetSymbolAddress((void**)&wf,   g_wf);
    cudaGetSymbolAddress((void**)&xf,   g_xf);
    cudaGetSymbolAddress((void**)&aggf, g_aggf);
    cudaGetSymbolAddress((void**)&tf,   g_tf);
    cudaGetSymbolAddress((void**)&hf16, g_hf16);

    cudaFuncSetAttribute(gemm_mma, cudaFuncAttributeMaxDynamicSharedMemorySize, GEMM_SMEM);
    cudaFuncSetAttribute(hw_gemm, cudaFuncAttributeMaxDynamicSharedMemorySize, HW_SMEM);

    const int M = NN, E = EE;
    const int TPB = 256;
    const int NBLK = (NB + 1023) / 1024;
    dim3 rgc_grid((M + 127) / 128, 2);
    dim3 hw_grid((M + 127) / 128, 2);
    int agg_grid = (NB * 32 + TPB - 1) / TPB;

    // ---- CSR build ----
    zero_deg_pos<<<(NB + TPB - 1) / TPB, TPB>>>();
    count_kernel<<<(E + TPB - 1) / TPB, TPB>>>(dst, rel, E);
    scan_block<<<NBLK, 256>>>(deg, off, bsum, NB);
    scan_block<<<1, 256>>>(bsum, bsum, nullptr, NBLK);
    scan_add<<<NBLK, 256>>>(off, bsum, NB);
    place_kernel<<<(E + TPB - 1) / TPB, TPB>>>(src, dst, rel, E);

    // ---- weight/x fp16 convert ----
    split_all_w<<<dim3(256, 8), 256>>>(rel_w1, loop_w1, hp_w1, ht_w1,
                                       rel_w2, loop_w2, hp_w2, ht_w2);
    convert_x<<<(NN * DIN + 255) / 256, 256>>>(x, NN * DIN);

    // ---- layer 1 ----
    agg_gather<DIN><<<agg_grid, TPB>>>(xf);
    gemm_mma<<<rgc_grid, 256, GEMM_SMEM>>>(
        aggf, RR * DIN, wf + OW_REL1,
        xf, DIN, wf + OW_LOOP1,
        rel_b1, loop_b1, tf, M, DH);
    hw_gemm<<<hw_grid, 512, HW_SMEM>>>(
        tf, wf + OW_HP1, wf + OW_HT1,
        hp_b1, ht_b1, nullptr, hf16, M);

    // ---- layer 2 ----
    agg_gather<DH><<<agg_grid, TPB>>>(hf16);
    gemm_mma<<<rgc_grid, 256, GEMM_SMEM>>>(
        aggf, RR * DH, wf + OW_REL2,
        hf16, DH, wf + OW_LOOP2,
        rel_b2, loop_b2, tf, M, DH);
    hw_gemm<<<hw_grid, 512, HW_SMEM>>>(
        tf, wf + OW_HP2, wf + OW_HT2,
        hp_b2, ht_b2, out, nullptr, M);
}

// round 15
// speedup vs baseline: 1.2534x; 1.2534x over previous
#include <cuda_runtime.h>
#include <cuda_fp16.h>
#include <cstdint>
#include <cstddef>

#define NN   50000
#define EE   800000
#define RR   4
#define NB   (NN * RR)
#define DIN  128
#define DH   256
#define EPSF 1e-10f

// ---------------- scratch (static device globals) ------------------------------
__device__ int   g_deg[NB];
__device__ int   g_off[NB];
__device__ int   g_pos[NB];
__device__ int   g_bsum[256];
__device__ int   g_eidx[EE];

// single-plane fp16 operands
__device__ uint16_t g_xf[(size_t)NN * DIN];
__device__ uint16_t g_aggf[(size_t)NN * RR * DH];
__device__ uint16_t g_tf[(size_t)NN * DH];
__device__ uint16_t g_hf16[(size_t)NN * DH];

#define OW_REL1  0
#define OW_LOOP1 131072
#define OW_HP1   163840
#define OW_HT1   229376
#define OW_REL2  294912
#define OW_LOOP2 557056
#define OW_HP2   622592
#define OW_HT2   688128
#define WTOT     753664
__device__ uint16_t g_wf[WTOT];      // fp16 weights

// ---------------- CSR build ------------------------------------------------------
__global__ void zero_deg_pos() {
    int i = blockIdx.x * blockDim.x + threadIdx.x;
    if (i < NB) { g_deg[i] = 0; g_pos[i] = 0; }
}

__global__ void count_kernel(const int* __restrict__ dst, const int* __restrict__ rel, int E) {
    int e = blockIdx.x * blockDim.x + threadIdx.x;
    if (e < E) atomicAdd(&g_deg[dst[e] * RR + rel[e]], 1);
}

__global__ void scan_block(const int* __restrict__ in, int* __restrict__ out,
                           int* __restrict__ bsum, int n) {
    __shared__ int wsum[8];
    int base = blockIdx.x * 1024;
    int t = threadIdx.x;
    int lane = t & 31, w = t >> 5;
    int v[4], s = 0;
#pragma unroll
    for (int j = 0; j < 4; j++) {
        int i = base + t * 4 + j;
        v[j] = (i < n) ? in[i] : 0;
        s += v[j];
    }
    int ps = s;
#pragma unroll
    for (int d = 1; d < 32; d <<= 1) {
        int y = __shfl_up_sync(~0u, ps, d);
        if (lane >= d) ps += y;
    }
    if (lane == 31) wsum[w] = ps;
    __syncthreads();
    if (w == 0) {
        int x = (lane < 8) ? wsum[lane] : 0;
#pragma unroll
        for (int d = 1; d < 8; d <<= 1) {
            int y = __shfl_up_sync(~0u, x, d);
            if (lane >= d) x += y;
        }
        if (lane < 8) wsum[lane] = x;
    }
    __syncthreads();
    int excl = ps - s + (w > 0 ? wsum[w - 1] : 0);
#pragma unroll
    for (int j = 0; j < 4; j++) {
        int i = base + t * 4 + j;
        if (i < n) out[i] = excl;
        excl += v[j];
    }
    if (t == 255 && bsum) bsum[blockIdx.x] = (w > 0 ? wsum[w - 1] : 0) + ps;
}

__global__ void scan_add(int* __restrict__ off, const int* __restrict__ bsum, int n) {
    int i = blockIdx.x * 1024 + threadIdx.x * 4;
    int a = bsum[blockIdx.x];
#pragma unroll
    for (int j = 0; j < 4; j++)
        if (i + j < n) off[i + j] += a;
}

__global__ void place_kernel(const int* __restrict__ src, const int* __restrict__ dst,
                             const int* __restrict__ rel, int E) {
    int e = blockIdx.x * blockDim.x + threadIdx.x;
    if (e >= E) return;
    int b = dst[e] * RR + rel[e];
    int slot = g_off[b] + atomicAdd(&g_pos[b], 1);
    g_eidx[slot] = src[e];
}

// ---------------- conversions -------------------------------------------------------
__global__ void split_all_w(const float* w0, const float* w1, const float* w2,
                            const float* w3, const float* w4, const float* w5,
                            const float* w6, const float* w7) {
    const int offs[8]  = {OW_REL1, OW_LOOP1, OW_HP1, OW_HT1,
                          OW_REL2, OW_LOOP2, OW_HP2, OW_HT2};
    const int sizes[8] = {131072, 32768, 65536, 65536, 262144, 65536, 65536, 65536};
    int seg = blockIdx.y;
    const float* w;
    switch (seg) {
        case 0: w = w0; break; case 1: w = w1; break;
        case 2: w = w2; break; case 3: w = w3; break;
        case 4: w = w4; break; case 5: w = w5; break;
        case 6: w = w6; break; default: w = w7; break;
    }
    int n = sizes[seg];
    int o = offs[seg];
    for (int i = blockIdx.x * blockDim.x + threadIdx.x; i < n; i += gridDim.x * blockDim.x)
        g_wf[o + i] = __half_as_ushort(__float2half_rn(w[i]));
}

__global__ void convert_x(const float* __restrict__ w, int n) {
    int i = blockIdx.x * blockDim.x + threadIdx.x;
    if (i >= n) return;
    g_xf[i] = __half_as_ushort(__float2half_rn(w[i]));
}

// ---------------- gather aggregation (fp16 source, MLP=4 unrolled) -------------------
template <int D>
__global__ void agg_gather(const uint16_t* __restrict__ xf) {
    constexpr int W32 = D / 64;               // uint32 words per lane: 2 or 4
    int gw = (blockIdx.x * blockDim.x + threadIdx.x) >> 5;
    int lane = threadIdx.x & 31;
    if (gw >= NB) return;
    int start = g_off[gw];
    int n = g_deg[gw];
    float acc[2 * W32];
#pragma unroll
    for (int j = 0; j < 2 * W32; ++j) acc[j] = 0.f;

    auto accum_word = [&](uint32_t w, int j) {
        __half2 h2 = *(__half2*)&w;
        float2 f = __half22float2(h2);
        acc[2 * j + 0] += f.x;
        acc[2 * j + 1] += f.y;
    };

    int k = 0;
    for (; k + 4 <= n; k += 4) {
        int s0 = g_eidx[start + k + 0];
        int s1 = g_eidx[start + k + 1];
        int s2 = g_eidx[start + k + 2];
        int s3 = g_eidx[start + k + 3];
        if (D == 256) {
            uint4 v0 = ((const uint4*)(xf + (size_t)s0 * D))[lane];
            uint4 v1 = ((const uint4*)(xf + (size_t)s1 * D))[lane];
            uint4 v2 = ((const uint4*)(xf + (size_t)s2 * D))[lane];
            uint4 v3 = ((const uint4*)(xf + (size_t)s3 * D))[lane];
            accum_word(v0.x, 0); accum_word(v0.y, 1); accum_word(v0.z, 2); accum_word(v0.w, 3);
            accum_word(v1.x, 0); accum_word(v1.y, 1); accum_word(v1.z, 2); accum_word(v1.w, 3);
            accum_word(v2.x, 0); accum_word(v2.y, 1); accum_word(v2.z, 2); accum_word(v2.w, 3);
            accum_word(v3.x, 0); accum_word(v3.y, 1); accum_word(v3.z, 2); accum_word(v3.w, 3);
        } else {
            uint2 v0 = ((const uint2*)(xf + (size_t)s0 * D))[lane];
            uint2 v1 = ((const uint2*)(xf + (size_t)s1 * D))[lane];
            uint2 v2 = ((const uint2*)(xf + (size_t)s2 * D))[lane];
            uint2 v3 = ((const uint2*)(xf + (size_t)s3 * D))[lane];
            accum_word(v0.x, 0); accum_word(v0.y, 1);
            accum_word(v1.x, 0); accum_word(v1.y, 1);
            accum_word(v2.x, 0); accum_word(v2.y, 1);
            accum_word(v3.x, 0); accum_word(v3.y, 1);
        }
    }
    for (; k + 2 <= n; k += 2) {
        int s0 = g_eidx[start + k + 0];
        int s1 = g_eidx[start + k + 1];
        if (D == 256) {
            uint4 v0 = ((const uint4*)(xf + (size_t)s0 * D))[lane];
            uint4 v1 = ((const uint4*)(xf + (size_t)s1 * D))[lane];
            accum_word(v0.x, 0); accum_word(v0.y, 1); accum_word(v0.z, 2); accum_word(v0.w, 3);
            accum_word(v1.x, 0); accum_word(v1.y, 1); accum_word(v1.z, 2); accum_word(v1.w, 3);
        } else {
            uint2 v0 = ((const uint2*)(xf + (size_t)s0 * D))[lane];
            uint2 v1 = ((const uint2*)(xf + (size_t)s1 * D))[lane];
            accum_word(v0.x, 0); accum_word(v0.y, 1);
            accum_word(v1.x, 0); accum_word(v1.y, 1);
        }
    }
    if (k < n) {
        int s0 = g_eidx[start + k];
        if (D == 256) {
            uint4 v0 = ((const uint4*)(xf + (size_t)s0 * D))[lane];
            accum_word(v0.x, 0); accum_word(v0.y, 1); accum_word(v0.z, 2); accum_word(v0.w, 3);
        } else {
            uint2 v0 = ((const uint2*)(xf + (size_t)s0 * D))[lane];
            accum_word(v0.x, 0); accum_word(v0.y, 1);
        }
    }

    float inv = 1.0f / ((float)n + EPSF);
    uint32_t o[W32];
#pragma unroll
    for (int j = 0; j < W32; ++j) {
        __half2 h2 = __floats2half2_rn(acc[2 * j] * inv, acc[2 * j + 1] * inv);
        o[j] = *(uint32_t*)&h2;
    }
    if (D == 256) {
        uint4 v = make_uint4(o[0], o[1], o[2], o[3]);
        ((uint4*)(g_aggf + (size_t)gw * D))[lane] = v;
    } else {
        uint2 v = make_uint2(o[0], o[1]);
        ((uint2*)(g_aggf + (size_t)gw * D))[lane] = v;
    }
}

// ---------------- mma.sync / cp.async helpers ----------------------------------------
__device__ __forceinline__ uint32_t smem_u32(const void* p) {
    uint32_t a;
    asm("{ .reg .u64 t; cvta.to.shared.u64 t, %1; cvt.u32.u64 %0, t; }" : "=r"(a) : "l"(p));
    return a;
}
__device__ __forceinline__ void ldsm_x4(uint32_t* r, uint32_t addr) {
    asm volatile("ldmatrix.sync.aligned.m8n8.x4.shared.b16 {%0,%1,%2,%3}, [%4];"
                 : "=r"(r[0]), "=r"(r[1]), "=r"(r[2]), "=r"(r[3]) : "r"(addr));
}
__device__ __forceinline__ void ldsm_x4_t(uint32_t* r, uint32_t addr) {
    asm volatile("ldmatrix.sync.aligned.m8n8.x4.trans.shared.b16 {%0,%1,%2,%3}, [%4];"
                 : "=r"(r[0]), "=r"(r[1]), "=r"(r[2]), "=r"(r[3]) : "r"(addr));
}
__device__ __forceinline__ void mma_f16(float* d, const uint32_t* a, uint32_t b0, uint32_t b1) {
    asm volatile(
        "mma.sync.aligned.m16n8k16.row.col.f32.f16.f16.f32 "
        "{%0,%1,%2,%3}, {%4,%5,%6,%7}, {%8,%9}, {%0,%1,%2,%3};"
        : "+f"(d[0]), "+f"(d[1]), "+f"(d[2]), "+f"(d[3])
        : "r"(a[0]), "r"(a[1]), "r"(a[2]), "r"(a[3]), "r"(b0), "r"(b1));
}
__device__ __forceinline__ void cp16(uint32_t dst, const void* src, bool pred) {
    int sz = pred ? 16 : 0;
    asm volatile("cp.async.cg.shared.global [%0], [%1], 16, %2;"
                 :: "r"(dst), "l"(src), "r"(sz) : "memory");
}
#define CP_COMMIT() asm volatile("cp.async.commit_group;" ::: "memory")
#define CP_WAIT1()  asm volatile("cp.async.wait_group 1;" ::: "memory")

// ---------------- RGC dual-A GEMM (fp16 single-plane, 2 CTAs/SM) -----------------------
#define NSTG 3
#define A_STRIDE 48
#define A_BYTES  (128 * A_STRIDE)          // 6144
#define B_BYTES  4096
#define STAGE_BYTES (A_BYTES + B_BYTES)    // 10240
#define GEMM_SMEM (NSTG * STAGE_BYTES)     // 30720

__global__ void __launch_bounds__(256, 2)
gemm_mma(const uint16_t* __restrict__ A1f, int K1, const uint16_t* __restrict__ W1,
         const uint16_t* __restrict__ A2f, int K2, const uint16_t* __restrict__ W2,
         const float* __restrict__ b1, const float* __restrict__ b2,
         uint16_t* __restrict__ Cf16, int M, int ldc) {
    extern __shared__ char sm[];
    uint32_t smBase = smem_u32(sm);

    int tid  = threadIdx.x;
    int warp = tid >> 5;
    int lane = tid & 31;
    int warpM = warp >> 1;
    int warpN = warp & 1;
    int rowBase = blockIdx.x * 128;
    int colBase = blockIdx.y * 128;

    float acc[2][8][4];
#pragma unroll
    for (int i = 0; i < 2; i++)
#pragma unroll
        for (int j = 0; j < 8; j++)
#pragma unroll
            for (int q = 0; q < 4; q++) acc[i][j][q] = 0.f;

    int nt1 = K1 >> 4, nt2 = K2 >> 4;
    int nt = nt1 + nt2;

    int aRow  = tid >> 1, aHalf = tid & 1;
    int bR    = (tid >> 4) & 15;
    int bC16  = tid & 15;

    auto issue_stage = [&](int t) {
        uint32_t stg = smBase + (uint32_t)(t % NSTG) * STAGE_BYTES;
        const uint16_t *Af, *W;
        int K, k0;
        if (t < nt1) { Af = A1f; W = W1; K = K1; k0 = t * 16; }
        else { Af = A2f; W = W2; K = K2; k0 = (t - nt1) * 16; }
        {
            int gr = rowBase + aRow;
            bool ok = gr < M;
            int grc = ok ? gr : (M - 1);
            cp16(stg + aRow * A_STRIDE + aHalf * 16,
                 Af + (size_t)grc * K + k0 + aHalf * 8, ok);
        }
        {
            uint32_t dst = stg + A_BYTES + bR * 256
                         + ((uint32_t)(bC16 * 16) ^ ((bR & 7) << 4));
            cp16(dst, W + (size_t)(k0 + bR) * DH + colBase + bC16 * 8, true);
        }
    };

    issue_stage(0); CP_COMMIT();
    if (nt > 1) issue_stage(1);
    CP_COMMIT();

    for (int t = 0; t < nt; ++t) {
        CP_WAIT1();
        __syncthreads();

        if (t + 2 < nt) issue_stage(t + 2);
        CP_COMMIT();

        uint32_t stg = smBase + (uint32_t)(t % NSTG) * STAGE_BYTES;
        uint32_t aBase = stg;
        uint32_t bBase = stg + A_BYTES;

        uint32_t a[2][4];
#pragma unroll
        for (int mt = 0; mt < 2; ++mt) {
            int row = warpM * 32 + mt * 16 + (lane & 15);
            uint32_t ad = aBase + row * A_STRIDE + (lane >> 4) * 16;
            ldsm_x4(a[mt], ad);
        }
#pragma unroll
        for (int bt = 0; bt < 4; ++bt) {
            int k = lane & 15;
            uint32_t cb = (uint32_t)(warpN * 128 + bt * 32 + (lane >> 4) * 16);
            uint32_t bd = bBase + k * 256 + (cb ^ ((k & 7) << 4));
            uint32_t b[4];
            ldsm_x4_t(b, bd);
#pragma unroll
            for (int mt = 0; mt < 2; ++mt) {
                mma_f16(acc[mt][bt * 2 + 0], a[mt], b[0], b[1]);
                mma_f16(acc[mt][bt * 2 + 1], a[mt], b[2], b[3]);
            }
        }
        __syncthreads();
    }

    // epilogue: relu(acc + b1 + b2) -> fp16 plane
#pragma unroll
    for (int mt = 0; mt < 2; ++mt) {
        int r0 = rowBase + warpM * 32 + mt * 16 + (lane >> 2);
#pragma unroll
        for (int j = 0; j < 8; ++j) {
            int col = colBase + warpN * 64 + j * 8 + (lane & 3) * 2;
            float bias0 = b1[col] + b2[col];
            float bias1 = b1[col + 1] + b2[col + 1];
            float v0 = fmaxf(acc[mt][j][0] + bias0, 0.f);
            float v1 = fmaxf(acc[mt][j][1] + bias1, 0.f);
            float v2 = fmaxf(acc[mt][j][2] + bias0, 0.f);
            float v3 = fmaxf(acc[mt][j][3] + bias1, 0.f);
            if (r0 < M)
                *(uint32_t*)(Cf16 + (size_t)r0 * ldc + col) =
                    (uint32_t)__half_as_ushort(__float2half_rn(v0)) |
                    ((uint32_t)__half_as_ushort(__float2half_rn(v1)) << 16);
            if (r0 + 8 < M)
                *(uint32_t*)(Cf16 + (size_t)(r0 + 8) * ldc + col) =
                    (uint32_t)__half_as_ushort(__float2half_rn(v2)) |
                    ((uint32_t)__half_as_ushort(__float2half_rn(v3)) << 16);
        }
    }
}

// ---------------- fused highway GEMM (fp16 single-plane) -------------------------------
#define HW_NT 16
#define HWB_BYTES 8192
#define HW_STAGE (A_BYTES + HWB_BYTES)     // 14336
#define HW_SMEM (NSTG * HW_STAGE)          // 43008

__global__ void __launch_bounds__(512, 1)
hw_gemm(const uint16_t* __restrict__ Af,
        const uint16_t* __restrict__ Wp, const uint16_t* __restrict__ Wg,
        const float* __restrict__ bp, const float* __restrict__ bg,
        float* __restrict__ hf, uint16_t* __restrict__ hf16, int M) {
    extern __shared__ char sm[];
    uint32_t smBase = smem_u32(sm);

    int tid  = threadIdx.x;
    int warp = tid >> 5;
    int lane = tid & 31;
    int warpM = warp >> 2;
    int warpN = warp & 3;
    int rowBase = blockIdx.x * 128;
    int colBase = blockIdx.y * 128;

    float accp[2][4][4], accg[2][4][4];
#pragma unroll
    for (int i = 0; i < 2; i++)
#pragma unroll
        for (int j = 0; j < 4; j++)
#pragma unroll
            for (int q = 0; q < 4; q++) { accp[i][j][q] = 0.f; accg[i][j][q] = 0.f; }

    auto issue_stage = [&](int t) {
        uint32_t stg = smBase + (uint32_t)(t % NSTG) * HW_STAGE;
        int k0 = t * 16;
        if (tid < 256) {
            int aRow = tid >> 1, aHalf = tid & 1;
            int gr = rowBase + aRow;
            bool ok = gr < M;
            int grc = ok ? gr : (M - 1);
            cp16(stg + aRow * A_STRIDE + aHalf * 16,
                 Af + (size_t)grc * DH + k0 + aHalf * 8, ok);
        }
        {
            int set = tid >> 8;
            int r   = (tid >> 4) & 15;
            int c16 = tid & 15;
            const uint16_t* base = set ? Wg : Wp;
            uint32_t dst = stg + A_BYTES + set * 4096 + r * 256
                         + ((uint32_t)(c16 * 16) ^ ((r & 7) << 4));
            cp16(dst, base + (size_t)(k0 + r) * DH + colBase + c16 * 8, true);
        }
    };

    issue_stage(0); CP_COMMIT();
    issue_stage(1); CP_COMMIT();

    for (int t = 0; t < HW_NT; ++t) {
        CP_WAIT1();
        __syncthreads();

        if (t + 2 < HW_NT) issue_stage(t + 2);
        CP_COMMIT();

        uint32_t stg = smBase + (uint32_t)(t % NSTG) * HW_STAGE;
        uint32_t aBase = stg;
        uint32_t bBase = stg + A_BYTES;

        uint32_t a[2][4];
#pragma unroll
        for (int mt = 0; mt < 2; ++mt) {
            int row = warpM * 32 + mt * 16 + (lane & 15);
            uint32_t ad = aBase + row * A_STRIDE + (lane >> 4) * 16;
            ldsm_x4(a[mt], ad);
        }
        int k = lane & 15;
#pragma unroll
        for (int bt = 0; bt < 2; ++bt) {
            uint32_t cb = (uint32_t)(warpN * 64 + bt * 32 + (lane >> 4) * 16);
            uint32_t bd0 = bBase + k * 256 + (cb ^ ((k & 7) << 4));
            uint32_t b[4];
            ldsm_x4_t(b, bd0);                 // proj
#pragma unroll
            for (int mt = 0; mt < 2; ++mt) {
                mma_f16(accp[mt][bt * 2 + 0], a[mt], b[0], b[1]);
                mma_f16(accp[mt][bt * 2 + 1], a[mt], b[2], b[3]);
            }
            ldsm_x4_t(b, bd0 + 4096);          // gate
#pragma unroll
            for (int mt = 0; mt < 2; ++mt) {
                mma_f16(accg[mt][bt * 2 + 0], a[mt], b[0], b[1]);
                mma_f16(accg[mt][bt * 2 + 1], a[mt], b[2], b[3]);
            }
        }
        __syncthreads();
    }

    // fused highway epilogue (t residual re-read from fp16 plane)
#pragma unroll
    for (int mt = 0; mt < 2; ++mt) {
        int r0 = rowBase + warpM * 32 + mt * 16 + (lane >> 2);
#pragma unroll
        for (int j = 0; j < 4; ++j) {
            int col = colBase + warpN * 32 + j * 8 + (lane & 3) * 2;
            float bp0 = bp[col], bp1 = bp[col + 1];
            float bg0 = bg[col], bg1 = bg[col + 1];
#pragma unroll
            for (int half = 0; half < 2; ++half) {
                int r = r0 + half * 8;
                if (r >= M) continue;
                float p0 = fmaxf(accp[mt][j][half * 2 + 0] + bp0, 0.f);
                float p1 = fmaxf(accp[mt][j][half * 2 + 1] + bp1, 0.f);
                float q0 = accg[mt][j][half * 2 + 0] + bg0;
                float q1 = accg[mt][j][half * 2 + 1] + bg1;
                float s0 = 1.0f / (1.0f + expf(-q0));
                float s1 = 1.0f / (1.0f + expf(-q1));
                uint32_t tw = *(const uint32_t*)(Af + (size_t)r * DH + col);
                float t0 = __half2float(__ushort_as_half((uint16_t)(tw & 0xFFFF)));
                float t1 = __half2float(__ushort_as_half((uint16_t)(tw >> 16)));
                float v0 = s0 * p0 + (1.0f - s0) * t0;
                float v1 = s1 * p1 + (1.0f - s1) * t1;
                if (hf) *(float2*)(hf + (size_t)r * DH + col) = make_float2(v0, v1);
                if (hf16)
                    *(uint32_t*)(hf16 + (size_t)r * DH + col) =
                        (uint32_t)__half_as_ushort(__float2half_rn(v0)) |
                        ((uint32_t)__half_as_ushort(__float2half_rn(v1)) << 16);
            }
        }
    }
}

// ---------------- launcher ------------------------------------------------------------
extern "C" void kernel_launch(void* const* d_in, const int* in_sizes, int n_in,
                              void* d_out, int out_size) {
    const float* x       = (const float*)d_in[0];
    const int*   src     = (const int*)d_in[1];
    const int*   dst     = (const int*)d_in[2];
    const int*   rel     = (const int*)d_in[3];
    const float* rel_w1  = (const float*)d_in[4];
    const float* rel_b1  = (const float*)d_in[5];
    const float* loop_w1 = (const float*)d_in[6];
    const float* loop_b1 = (const float*)d_in[7];
    const float* hp_w1   = (const float*)d_in[8];
    const float* hp_b1   = (const float*)d_in[9];
    const float* ht_w1   = (const float*)d_in[10];
    const float* ht_b1   = (const float*)d_in[11];
    const float* rel_w2  = (const float*)d_in[12];
    const float* rel_b2  = (const float*)d_in[13];
    const float* loop_w2 = (const float*)d_in[14];
    const float* loop_b2 = (const float*)d_in[15];
    const float* hp_w2   = (const float*)d_in[16];
    const float* hp_b2   = (const float*)d_in[17];
    const float* ht_w2   = (const float*)d_in[18];
    const float* ht_b2   = (const float*)d_in[19];
    float* out = (float*)d_out;

    int *deg, *off, *pos, *bsum;
    uint16_t *wf, *xf, *aggf, *tf, *hf16;
    cudaGetSymbolAddress((void**)&deg,  g_deg);
    cudaGetSymbolAddress((void**)&off,  g_off);
    cudaGetSymbolAddress((void**)&pos,  g_pos);
    cudaGetSymbolAddress((void**)&bsum, g_bsum);
    cudaGetSymbolAddress((void**)&wf,   g_wf);
    cudaGetSymbolAddress((void**)&xf,   g_xf);
    cudaGetSymbolAddress((void**)&aggf, g_aggf);
    cudaGetSymbolAddress((void**)&tf,   g_tf);
    cudaGetSymbolAddress((void**)&hf16, g_hf16);

    cudaFuncSetAttribute(gemm_mma, cudaFuncAttributeMaxDynamicSharedMemorySize, GEMM_SMEM);
    cudaFuncSetAttribute(hw_gemm, cudaFuncAttributeMaxDynamicSharedMemorySize, HW_SMEM);

    const int M = NN, E = EE;
    const int TPB = 256;
    const int NBLK = (NB + 1023) / 1024;
    dim3 rgc_grid((M + 127) / 128, 2);
    dim3 hw_grid((M + 127) / 128, 2);
    int agg_grid = (NB * 32 + TPB - 1) / TPB;

    // ---- CSR build ----
    zero_deg_pos<<<(NB + TPB - 1) / TPB, TPB>>>();
    count_kernel<<<(E + TPB - 1) / TPB, TPB>>>(dst, rel, E);
    scan_block<<<NBLK, 256>>>(deg, off, bsum, NB);
    scan_block<<<1, 256>>>(bsum, bsum, nullptr, NBLK);
    scan_add<<<NBLK, 256>>>(off, bsum, NB);
    place_kernel<<<(E + TPB - 1) / TPB, TPB>>>(src, dst, rel, E);

    // ---- weight/x fp16 convert ----
    split_all_w<<<dim3(256, 8), 256>>>(rel_w1, loop_w1, hp_w1, ht_w1,
                                       rel_w2, loop_w2, hp_w2, ht_w2);
    convert_x<<<(NN * DIN + 255) / 256, 256>>>(x, NN * DIN);

    // ---- layer 1 ----
    agg_gather<DIN><<<agg_grid, TPB>>>(xf);
    gemm_mma<<<rgc_grid, 256, GEMM_SMEM>>>(
        aggf, RR * DIN, wf + OW_REL1,
        xf, DIN, wf + OW_LOOP1,
        rel_b1, loop_b1, tf, M, DH);
    hw_gemm<<<hw_grid, 512, HW_SMEM>>>(
        tf, wf + OW_HP1, wf + OW_HT1,
        hp_b1, ht_b1, nullptr, hf16, M);

    // ---- layer 2 ----
    agg_gather<DH><<<agg_grid, TPB>>>(hf16);
    gemm_mma<<<rgc_grid, 256, GEMM_SMEM>>>(
        aggf, RR * DH, wf + OW_REL2,
        hf16, DH, wf + OW_LOOP2,
        rel_b2, loop_b2, tf, M, DH);
    hw_gemm<<<hw_grid, 512, HW_SMEM>>>(
        tf, wf + OW_HP2, wf + OW_HT2,
        hp_b2, ht_b2, out, nullptr, M);
}